// round 6
// baseline (speedup 1.0000x reference)
#include <cuda_runtime.h>
#include <cuda_fp16.h>
#include <cstdint>

#define NSTATES 512
#define MSYMS   256
#define BATCHN  256
#define TLEN    256

#define GB 8                 // batch groups
#define GI 16                // i-slices
#define NCTA (GB*GI)         // 128 CTAs
#define NT 256               // 8 warps

#define ESTR 520             // fp16 row stride (1040B) — conflict-free, 16B aligned

// ---- dynamic SMEM layout (bytes) ----
#define MB_OFF    0                      // float[32]
#define SC_OFF    128                    // __half2 scales [32][16] = 2048B
#define BUF_OFF   2304                   // float[8][16][18] = 9216B
#define P_OFF     11520                  // 32 x 520 fp16 = 33280B
#define E_OFF     44800                  // 32 x 520 fp16 = 33280B
#define SYMS_OFF  78080                  // 32 x 256 int  = 32768B
#define SMEM_TOTAL 110848

// ---------------- device globals ----------------
__device__ __half gPh[NSTATES * NSTATES];   // column-softmax of transition, fp16
__device__ float  gLET[MSYMS * NSTATES];    // log emission transposed [sym][state]
__device__ float  gLP[NSTATES];             // log priors
__device__ float  gColLse[NSTATES];
__device__ __half gEh[2][BATCHN][NSTATES];  // exp(alpha - tile_max), fp16, dbl-buffered
__device__ float  gM2[2][BATCHN][GI];       // per (b, i-tile) max
__device__ float  gS2[2][BATCHN][GI];       // per (b, i-tile) sum
__device__ int    g_flag[GB][32];           // per-group publish flags (128B rows)

// ---------------- PTX helpers (baseline ISA only) ----------------
__device__ __forceinline__ uint32_t smem_u32(const void* p) {
    uint32_t a;
    asm("{ .reg .u64 t; cvta.to.shared.u64 t, %1; cvt.u32.u64 %0, t; }" : "=r"(a) : "l"(p));
    return a;
}
__device__ __forceinline__ int ld_acq(const int* p) {
    int v; asm volatile("ld.acquire.gpu.global.s32 %0, [%1];" : "=r"(v) : "l"(p)); return v;
}
__device__ __forceinline__ void st_rel(int* p, int v) {
    asm volatile("st.release.gpu.global.s32 [%0], %1;" :: "l"(p), "r"(v) : "memory");
}
__device__ __forceinline__ void ldsm4(uint32_t& r0, uint32_t& r1, uint32_t& r2, uint32_t& r3,
                                      uint32_t addr) {
    asm volatile("ldmatrix.sync.aligned.m8n8.x4.shared.b16 {%0,%1,%2,%3}, [%4];"
                 : "=r"(r0), "=r"(r1), "=r"(r2), "=r"(r3) : "r"(addr));
}
__device__ __forceinline__ void mma16816(float& d0, float& d1, float& d2, float& d3,
                                         uint32_t a0, uint32_t a1, uint32_t a2, uint32_t a3,
                                         uint32_t b0, uint32_t b1) {
    asm volatile(
        "mma.sync.aligned.m16n8k16.row.col.f32.f16.f16.f32 "
        "{%0,%1,%2,%3}, {%4,%5,%6,%7}, {%8,%9}, {%0,%1,%2,%3};"
        : "+f"(d0), "+f"(d1), "+f"(d2), "+f"(d3)
        : "r"(a0), "r"(a1), "r"(a2), "r"(a3), "r"(b0), "r"(b1));
}

// ---------------- prep kernels ----------------
__global__ void k_reset() {
    int i = threadIdx.x;
    if (i < GB * 32) ((int*)g_flag)[i] = -1;
}

__global__ void k_prep_emission(const float* __restrict__ em) {
    __shared__ float red[MSYMS];
    int n = blockIdx.x, t = threadIdx.x;
    float x = em[n * MSYMS + t];
    red[t] = x; __syncthreads();
    for (int s = MSYMS / 2; s > 0; s >>= 1) { if (t < s) red[t] = fmaxf(red[t], red[t + s]); __syncthreads(); }
    float m = red[0]; __syncthreads();
    red[t] = __expf(x - m); __syncthreads();
    for (int s = MSYMS / 2; s > 0; s >>= 1) { if (t < s) red[t] += red[t + s]; __syncthreads(); }
    float lse = m + __logf(red[0]);
    gLET[t * NSTATES + n] = x - lse;
}

__global__ void k_prep_tstats(const float* __restrict__ tr) {
    __shared__ float red[256];
    int k = blockIdx.x, t = threadIdx.x;
    float x0 = tr[t * NSTATES + k];
    float x1 = tr[(t + 256) * NSTATES + k];
    red[t] = fmaxf(x0, x1); __syncthreads();
    for (int s = 128; s > 0; s >>= 1) { if (t < s) red[t] = fmaxf(red[t], red[t + s]); __syncthreads(); }
    float m = red[0]; __syncthreads();
    red[t] = __expf(x0 - m) + __expf(x1 - m); __syncthreads();
    for (int s = 128; s > 0; s >>= 1) { if (t < s) red[t] += red[t + s]; __syncthreads(); }
    if (t == 0) gColLse[k] = m + __logf(red[0]);
}

__global__ void k_prep_P(const float* __restrict__ tr) {
    int i = blockIdx.x, k = threadIdx.x;
    gPh[i * NSTATES + k] = __float2half_rn(__expf(tr[i * NSTATES + k] - gColLse[k]));
}

__global__ void k_prep_priors(const float* __restrict__ pr) {
    __shared__ float red[NSTATES];
    int t = threadIdx.x;
    float x = pr[t];
    red[t] = x; __syncthreads();
    for (int s = 256; s > 0; s >>= 1) { if (t < s) red[t] = fmaxf(red[t], red[t + s]); __syncthreads(); }
    float m = red[0]; __syncthreads();
    red[t] = __expf(x - m); __syncthreads();
    for (int s = 256; s > 0; s >>= 1) { if (t < s) red[t] += red[t + s]; __syncthreads(); }
    gLP[t] = x - (m + __logf(red[0]));
}

// ---------------- forward kernel ----------------
extern __shared__ char sm_raw[];

__global__ void __launch_bounds__(NT, 1) forward_kernel(const int* __restrict__ batch,
                                                        float* __restrict__ out) {
    char* sm = sm_raw;
    const uint32_t smem_base = smem_u32(sm);
    float*   sm_mb  = (float*)(sm + MB_OFF);      // [32]
    __half2* sm_sch = (__half2*)(sm + SC_OFF);    // [32][16] half2 scales
    float*   buf    = (float*)(sm + BUF_OFF);     // [8][16][18]
    int*     syms   = (int*)(sm + SYMS_OFF);      // [32][256]
    const uint32_t P_base = smem_base + P_OFF;
    const uint32_t E_base = smem_base + E_OFF;

    const int tid  = threadIdx.x;
    const int lane = tid & 31;
    const int w    = tid >> 5;
    const int g    = blockIdx.x >> 4;   // 0..7 batch group
    const int j    = blockIdx.x & 15;   // 0..15 i-slice
    int* flags = &g_flag[g][0];

    // stats/staging/epilogue mapping: thread owns (b, ...)
    const int b  = tid >> 3;            // 0..31
    const int u  = tid & 7;             // 0..7
    const int i4 = (tid & 7) * 4;       // epilogue i-quad
    const int gb = g * 32 + b;

    // warp tile decomposition: m16 x n16 x k256
    const int mi = w & 1, ni = (w >> 1) & 1, kh = (w >> 2) & 1;
    const int kbase = kh * 256;

    // ---------------- prologue ----------------
    // P j-slice -> SMEM (padded rows)
    {
        const __half* src = &gPh[(j * 32 + b) * NSTATES];
        char* dst = sm + P_OFF + b * (ESTR * 2);
        #pragma unroll
        for (int c8 = 0; c8 < 8; c8++) {
            int c = u + 8 * c8;                           // 16B chunk 0..63
            *(uint4*)(dst + c * 16) = *(const uint4*)(src + c * 8);
        }
    }
    // symbols
    for (int idx = tid; idx < 32 * TLEN; idx += NT)
        syms[idx] = batch[(g * 32 + (idx >> 8)) * TLEN + (idx & 255)];
    __syncthreads();

    // A fragments resident in registers for all steps
    uint32_t a[16][4];
    {
        const int arow  = mi * 16 + (lane & 15);
        const int akoff = (lane >> 4) * 8;
        #pragma unroll
        for (int kk = 0; kk < 16; kk++) {
            uint32_t addr = P_base + (uint32_t)((arow * ESTR + kbase + kk * 16 + akoff) * 2);
            ldsm4(a[kk][0], a[kk][1], a[kk][2], a[kk][3], addr);
        }
    }

    // B ldmatrix address base
    const int brow = ni * 16 + (lane >> 4) * 8 + (lane & 7);
    const int bk0  = ((lane >> 3) & 1) * 8 + kbase;
    const uint32_t b_addr0 = E_base + (uint32_t)((brow * ESTR + bk0) * 2);

    // ---------------- step 0 ----------------
    {
        int sy = syms[b * TLEN + 0];
        float4 lt = *(const float4*)&gLET[sy * NSTATES + j * 32 + i4];
        float4 lp = *(const float4*)&gLP[j * 32 + i4];
        float v0 = lt.x + lp.x, v1 = lt.y + lp.y, v2 = lt.z + lp.z, v3 = lt.w + lp.w;
        float m = fmaxf(fmaxf(v0, v1), fmaxf(v2, v3));
        #pragma unroll
        for (int o = 4; o > 0; o >>= 1) m = fmaxf(m, __shfl_xor_sync(0xffffffffu, m, o));
        float e0 = __expf(v0 - m), e1 = __expf(v1 - m), e2 = __expf(v2 - m), e3 = __expf(v3 - m);
        float s = e0 + e1 + e2 + e3;
        #pragma unroll
        for (int o = 4; o > 0; o >>= 1) s += __shfl_xor_sync(0xffffffffu, s, o);
        union { __half2 h[2]; uint2 uu; } cv;
        cv.h[0] = __floats2half2_rn(e0, e1);
        cv.h[1] = __floats2half2_rn(e2, e3);
        *(uint2*)&gEh[0][gb][j * 32 + i4] = cv.uu;
        if (u == 0) { gM2[0][gb][j] = m; gS2[0][gb][j] = s; }
        __syncthreads();
        if (tid == 0) st_rel(&flags[j], 0);
    }

    // ---------------- main loop ----------------
    for (int t = 1; t < TLEN; ++t) {
        const int p = (t - 1) & 1, q = t & 1;
        const int outj = (t - 1) & 15;

        // phase W: wait for all 16 producers to publish step t-1 (acquire)
        if (w == 0 && lane < 16) {
            const int* fp = &flags[lane];
            while (ld_acq(fp) < t - 1) { }
        }
        __syncthreads();

        // phase 0: issue long-latency loads first
        uint4 eraw[8];
        {
            const __half* esrc = &gEh[p][gb][0];
            #pragma unroll
            for (int c8 = 0; c8 < 8; c8++)
                eraw[c8] = *(const uint4*)(esrc + (u + 8 * c8) * 8);
        }
        int sy = syms[b * TLEN + t];
        float4 lt = *(const float4*)&gLET[sy * NSTATES + j * 32 + i4];

        // phase 1 (all threads): per-b global max + half2 tile scales
        {
            float2 mv = *(const float2*)&gM2[p][gb][2 * u];
            float mloc = fmaxf(mv.x, mv.y);
            #pragma unroll
            for (int o = 4; o > 0; o >>= 1)
                mloc = fmaxf(mloc, __shfl_xor_sync(0xffffffffu, mloc, o));
            float scx = __expf(mv.x - mloc), scy = __expf(mv.y - mloc);
            __half hx = __float2half_rn(scx), hy = __float2half_rn(scy);
            sm_sch[b * 16 + 2 * u]     = __halves2half2(hx, hx);
            sm_sch[b * 16 + 2 * u + 1] = __halves2half2(hy, hy);
            if (u == 0) sm_mb[b] = mloc;
            if (j == outj) {                       // rotating out-column owner
                float2 sv = *(const float2*)&gS2[p][gb][2 * u];
                float ps = scx * sv.x + scy * sv.y;
                #pragma unroll
                for (int o = 4; o > 0; o >>= 1)
                    ps += __shfl_xor_sync(0xffffffffu, ps, o);
                if (u == 0) out[gb * TLEN + (t - 1)] = mloc + __logf(ps);
            }
        }
        __syncthreads();

        float mbv = sm_mb[b];

        // phase 2: scale pre-loaded E (pure fp16 hmul2) and store to padded SMEM
        {
            char* edst = sm + E_OFF + b * (ESTR * 2);
            #pragma unroll
            for (int c8 = 0; c8 < 8; c8++) {
                int c = u + 8 * c8;                     // 8-half chunk, k = c*8
                __half2 sc2 = sm_sch[b * 16 + (c >> 2)];
                uint4 raw = eraw[c8];
                __half2* hp = (__half2*)&raw;
                hp[0] = __hmul2(hp[0], sc2);
                hp[1] = __hmul2(hp[1], sc2);
                hp[2] = __hmul2(hp[2], sc2);
                hp[3] = __hmul2(hp[3], sc2);
                *(uint4*)(edst + c * 16) = raw;
            }
        }
        __syncthreads();

        // phase 3: HMMA contraction (A in regs, B from SMEM)
        float d0 = 0.f, d1 = 0.f, d2 = 0.f, d3 = 0.f;
        float d4 = 0.f, d5 = 0.f, d6 = 0.f, d7 = 0.f;
        #pragma unroll
        for (int kk = 0; kk < 16; kk++) {
            uint32_t r0, r1, r2, r3;
            ldsm4(r0, r1, r2, r3, b_addr0 + (uint32_t)(kk * 32));
            mma16816(d0, d1, d2, d3, a[kk][0], a[kk][1], a[kk][2], a[kk][3], r0, r1);
            mma16816(d4, d5, d6, d7, a[kk][0], a[kk][1], a[kk][2], a[kk][3], r2, r3);
        }

        // phase 4: stash split-k partials
        {
            int r1r = lane >> 2, c0 = (lane & 3) * 2;
            float* bw = &buf[w * 16 * 18];
            *(float2*)&bw[r1r * 18 + c0]           = make_float2(d0, d1);
            *(float2*)&bw[(r1r + 8) * 18 + c0]     = make_float2(d2, d3);
            *(float2*)&bw[r1r * 18 + c0 + 8]       = make_float2(d4, d5);
            *(float2*)&bw[(r1r + 8) * 18 + c0 + 8] = make_float2(d6, d7);
        }
        __syncthreads();

        // phase 5: epilogue — split-k add, log, +mb+em, publish
        {
            const int nib = b >> 4, cb = b & 15;
            const int mis = i4 >> 4, rbase = i4 & 15;
            const float* b0p = &buf[(mis + 2 * nib) * 288 + cb];
            const float* b1p = b0p + 4 * 288;
            float C0 = b0p[(rbase + 0) * 18] + b1p[(rbase + 0) * 18];
            float C1 = b0p[(rbase + 1) * 18] + b1p[(rbase + 1) * 18];
            float C2 = b0p[(rbase + 2) * 18] + b1p[(rbase + 2) * 18];
            float C3 = b0p[(rbase + 3) * 18] + b1p[(rbase + 3) * 18];
            float v0 = __logf(C0) + mbv + lt.x;
            float v1 = __logf(C1) + mbv + lt.y;
            float v2 = __logf(C2) + mbv + lt.z;
            float v3 = __logf(C3) + mbv + lt.w;
            float m = fmaxf(fmaxf(v0, v1), fmaxf(v2, v3));
            #pragma unroll
            for (int o = 4; o > 0; o >>= 1) m = fmaxf(m, __shfl_xor_sync(0xffffffffu, m, o));
            float e0 = __expf(v0 - m), e1 = __expf(v1 - m), e2 = __expf(v2 - m), e3 = __expf(v3 - m);
            float s = e0 + e1 + e2 + e3;
            #pragma unroll
            for (int o = 4; o > 0; o >>= 1) s += __shfl_xor_sync(0xffffffffu, s, o);
            union { __half2 h[2]; uint2 uu; } cv;
            cv.h[0] = __floats2half2_rn(e0, e1);
            cv.h[1] = __floats2half2_rn(e2, e3);
            *(uint2*)&gEh[q][gb][j * 32 + i4] = cv.uu;
            if (u == 0) { gM2[q][gb][j] = m; gS2[q][gb][j] = s; }
        }

        __syncthreads();
        if (tid == 0) st_rel(&flags[j], t);   // release: publishes E+stats of step t
    }

    // final output column t = 255 (buffer 1), owned by j == 15
    if (j == 15) {
        if (w == 0 && lane < 16) {
            const int* fp = &flags[lane];
            while (ld_acq(fp) < TLEN - 1) { }
        }
        __syncthreads();
        if (tid < 32) {
            const int p = (TLEN - 1) & 1;
            int gbb = g * 32 + tid;
            const float* mrow = &gM2[p][gbb][0];
            const float* srow = &gS2[p][gbb][0];
            float mb = mrow[0];
            #pragma unroll
            for (int jj = 1; jj < 16; jj++) mb = fmaxf(mb, mrow[jj]);
            float ssum = 0.f;
            #pragma unroll
            for (int jj = 0; jj < 16; jj++) ssum += __expf(mrow[jj] - mb) * srow[jj];
            out[gbb * TLEN + (TLEN - 1)] = mb + __logf(ssum);
        }
    }
}

// ---------------- launch ----------------
extern "C" void kernel_launch(void* const* d_in, const int* in_sizes, int n_in,
                              void* d_out, int out_size) {
    const int*   batch = (const int*)d_in[0];
    const float* em    = (const float*)d_in[1];
    const float* tr    = (const float*)d_in[2];
    const float* pr    = (const float*)d_in[3];
    float* out = (float*)d_out;

    cudaFuncSetAttribute(forward_kernel, cudaFuncAttributeMaxDynamicSharedMemorySize, SMEM_TOTAL);

    k_prep_emission<<<NSTATES, MSYMS>>>(em);
    k_prep_tstats<<<NSTATES, 256>>>(tr);
    k_prep_P<<<NSTATES, NSTATES>>>(tr);
    k_prep_priors<<<1, NSTATES>>>(pr);
    k_reset<<<1, 256>>>();
    forward_kernel<<<NCTA, NT, SMEM_TOTAL>>>(batch, out);
}

// round 7
// speedup vs baseline: 1.2083x; 1.2083x over previous
#include <cuda_runtime.h>
#include <cuda_fp16.h>
#include <cstdint>

#define NSTATES 512
#define MSYMS   256
#define BATCHN  256
#define TLEN    256

#define GB 8                 // batch groups
#define GI 16                // i-slices
#define NCTA (GB*GI)         // 128 CTAs
#define NT 256               // 8 warps

#define ESTR 520             // fp16 row stride (1040B) — conflict-free, 16B aligned

// ---- dynamic SMEM layout (bytes) ----
#define BUF_OFF   0                      // float[8][16][18] = 9216B
#define P_OFF     9216                   // 32 x 520 fp16 = 33280B
#define E_OFF     42496                  // 32 x 520 fp16 = 33280B
#define SYMS_OFF  75776                  // 32 x 256 int  = 32768B
#define SMEM_TOTAL 108544

// ---------------- device globals ----------------
__device__ __half gPh[NSTATES * NSTATES];   // column-softmax of transition, fp16
__device__ float  gLET[MSYMS * NSTATES];    // log emission transposed [sym][state]
__device__ float  gLP[NSTATES];             // log priors
__device__ __half gEh[2][BATCHN][NSTATES];  // exp(alpha - tile_max), fp16, dbl-buffered
__device__ float  gM2[2][BATCHN][GI];       // per (b, i-tile) max
__device__ float  gS2[2][BATCHN][GI];       // per (b, i-tile) sum
__device__ unsigned g_cnt_arr[GB * 32];     // per-group barrier counters, 128B apart

// ---------------- PTX helpers (baseline ISA only) ----------------
__device__ __forceinline__ uint32_t smem_u32(const void* p) {
    uint32_t a;
    asm("{ .reg .u64 t; cvta.to.shared.u64 t, %1; cvt.u32.u64 %0, t; }" : "=r"(a) : "l"(p));
    return a;
}
__device__ __forceinline__ void ldsm4(uint32_t& r0, uint32_t& r1, uint32_t& r2, uint32_t& r3,
                                      uint32_t addr) {
    asm volatile("ldmatrix.sync.aligned.m8n8.x4.shared.b16 {%0,%1,%2,%3}, [%4];"
                 : "=r"(r0), "=r"(r1), "=r"(r2), "=r"(r3) : "r"(addr));
}
__device__ __forceinline__ void mma16816(float& d0, float& d1, float& d2, float& d3,
                                         uint32_t a0, uint32_t a1, uint32_t a2, uint32_t a3,
                                         uint32_t b0, uint32_t b1) {
    asm volatile(
        "mma.sync.aligned.m16n8k16.row.col.f32.f16.f16.f32 "
        "{%0,%1,%2,%3}, {%4,%5,%6,%7}, {%8,%9}, {%0,%1,%2,%3};"
        : "+f"(d0), "+f"(d1), "+f"(d2), "+f"(d3)
        : "r"(a0), "r"(a1), "r"(a2), "r"(a3), "r"(b0), "r"(b1));
}

// ---------------- fused prep kernel (one launch) ----------------
// blocks 0..511: emission row n + transition column n (+ P column n)
// block 512:     priors + barrier-counter reset
__global__ void k_prep(const float* __restrict__ em, const float* __restrict__ tr,
                       const float* __restrict__ pr) {
    __shared__ float red[256];
    const int blk = blockIdx.x, t = threadIdx.x;

    if (blk < NSTATES) {
        // ---- emission log-softmax over row blk ----
        float x = em[blk * MSYMS + t];
        red[t] = x; __syncthreads();
        for (int s = 128; s > 0; s >>= 1) { if (t < s) red[t] = fmaxf(red[t], red[t + s]); __syncthreads(); }
        float m = red[0]; __syncthreads();
        red[t] = __expf(x - m); __syncthreads();
        for (int s = 128; s > 0; s >>= 1) { if (t < s) red[t] += red[t + s]; __syncthreads(); }
        float lse = m + __logf(red[0]);
        gLET[t * NSTATES + blk] = x - lse;
        __syncthreads();

        // ---- transition column blk: softmax over axis 0 -> P column (fp16) ----
        float x0 = tr[t * NSTATES + blk];
        float x1 = tr[(t + 256) * NSTATES + blk];
        red[t] = fmaxf(x0, x1); __syncthreads();
        for (int s = 128; s > 0; s >>= 1) { if (t < s) red[t] = fmaxf(red[t], red[t + s]); __syncthreads(); }
        float mm = red[0]; __syncthreads();
        red[t] = __expf(x0 - mm) + __expf(x1 - mm); __syncthreads();
        for (int s = 128; s > 0; s >>= 1) { if (t < s) red[t] += red[t + s]; __syncthreads(); }
        float clse = mm + __logf(red[0]);
        gPh[t * NSTATES + blk]         = __float2half_rn(__expf(x0 - clse));
        gPh[(t + 256) * NSTATES + blk] = __float2half_rn(__expf(x1 - clse));
    } else {
        // ---- priors log-softmax + reset ----
        float x0 = pr[t], x1 = pr[t + 256];
        red[t] = fmaxf(x0, x1); __syncthreads();
        for (int s = 128; s > 0; s >>= 1) { if (t < s) red[t] = fmaxf(red[t], red[t + s]); __syncthreads(); }
        float m = red[0]; __syncthreads();
        red[t] = __expf(x0 - m) + __expf(x1 - m); __syncthreads();
        for (int s = 128; s > 0; s >>= 1) { if (t < s) red[t] += red[t + s]; __syncthreads(); }
        float lse = m + __logf(red[0]);
        gLP[t]       = x0 - lse;
        gLP[t + 256] = x1 - lse;
        if (t < GB) g_cnt_arr[t * 32] = 0u;
    }
}

// ---------------- per-group barrier (16 CTAs per group) ----------------
__device__ __forceinline__ void groupbar(unsigned* cnt, unsigned target) {
    __syncthreads();
    if (threadIdx.x == 0) {
        __threadfence();
        atomicAdd(cnt, 1u);
        while (*(volatile unsigned*)cnt < target) { }
        __threadfence();
    }
    __syncthreads();
}

// ---------------- forward kernel ----------------
extern __shared__ char sm_raw[];

__global__ void __launch_bounds__(NT, 1) forward_kernel(const int* __restrict__ batch,
                                                        float* __restrict__ out) {
    char* sm = sm_raw;
    const uint32_t smem_base = smem_u32(sm);
    float* buf  = (float*)(sm + BUF_OFF);     // [8][16][18]
    int*   syms = (int*)(sm + SYMS_OFF);      // [32][256]
    const uint32_t P_base = smem_base + P_OFF;
    const uint32_t E_base = smem_base + E_OFF;

    const int tid  = threadIdx.x;
    const int lane = tid & 31;
    const int w    = tid >> 5;
    const int g    = blockIdx.x >> 4;   // 0..7 batch group
    const int j    = blockIdx.x & 15;   // 0..15 i-slice
    unsigned* my_cnt = &g_cnt_arr[g * 32];

    // stats/staging/epilogue mapping: thread owns (b, u)
    const int b  = tid >> 3;            // 0..31
    const int u  = tid & 7;             // 0..7
    const int i4 = u * 4;               // epilogue i-quad
    const int gb = g * 32 + b;
    const int octbase = lane & 24;      // first lane of this thread's octet (same b)

    // warp tile decomposition: m16 x n16 x k256
    const int mi = w & 1, ni = (w >> 1) & 1, kh = (w >> 2) & 1;
    const int kbase = kh * 256;

    // ---------------- prologue ----------------
    // P j-slice -> SMEM (padded rows)
    {
        const __half* src = &gPh[(j * 32 + b) * NSTATES];
        char* dst = sm + P_OFF + b * (ESTR * 2);
        #pragma unroll
        for (int c8 = 0; c8 < 8; c8++) {
            int c = u + 8 * c8;                           // 16B chunk 0..63
            *(uint4*)(dst + c * 16) = *(const uint4*)(src + c * 8);
        }
    }
    // symbols
    for (int idx = tid; idx < 32 * TLEN; idx += NT)
        syms[idx] = batch[(g * 32 + (idx >> 8)) * TLEN + (idx & 255)];
    __syncthreads();

    // A fragments resident in registers for all steps
    uint32_t a[16][4];
    {
        const int arow  = mi * 16 + (lane & 15);
        const int akoff = (lane >> 4) * 8;
        #pragma unroll
        for (int kk = 0; kk < 16; kk++) {
            uint32_t addr = P_base + (uint32_t)((arow * ESTR + kbase + kk * 16 + akoff) * 2);
            ldsm4(a[kk][0], a[kk][1], a[kk][2], a[kk][3], addr);
        }
    }

    // B ldmatrix address base
    const int brow = ni * 16 + (lane >> 4) * 8 + (lane & 7);
    const int bk0  = ((lane >> 3) & 1) * 8 + kbase;
    const uint32_t b_addr0 = E_base + (uint32_t)((brow * ESTR + bk0) * 2);

    unsigned target = GI;

    // ---------------- step 0 ----------------
    {
        int sy = syms[b * TLEN + 0];
        float4 lt = *(const float4*)&gLET[sy * NSTATES + j * 32 + i4];
        float4 lp = *(const float4*)&gLP[j * 32 + i4];
        float v0 = lt.x + lp.x, v1 = lt.y + lp.y, v2 = lt.z + lp.z, v3 = lt.w + lp.w;
        float m = fmaxf(fmaxf(v0, v1), fmaxf(v2, v3));
        #pragma unroll
        for (int o = 4; o > 0; o >>= 1) m = fmaxf(m, __shfl_xor_sync(0xffffffffu, m, o));
        float e0 = __expf(v0 - m), e1 = __expf(v1 - m), e2 = __expf(v2 - m), e3 = __expf(v3 - m);
        float s = e0 + e1 + e2 + e3;
        #pragma unroll
        for (int o = 4; o > 0; o >>= 1) s += __shfl_xor_sync(0xffffffffu, s, o);
        union { __half2 h[2]; uint2 uu; } cv;
        cv.h[0] = __floats2half2_rn(e0, e1);
        cv.h[1] = __floats2half2_rn(e2, e3);
        *(uint2*)&gEh[0][gb][j * 32 + i4] = cv.uu;
        if (u == 0) { gM2[0][gb][j] = m; gS2[0][gb][j] = s; }
        groupbar(my_cnt, target); target += GI;
    }

    // ---------------- main loop ----------------
    for (int t = 1; t < TLEN; ++t) {
        const int p = (t - 1) & 1, q = t & 1;
        const int outj = (t - 1) & 15;

        // phase 0: issue long-latency loads first
        uint4 eraw[8];
        {
            const __half* esrc = &gEh[p][gb][0];
            #pragma unroll
            for (int c8 = 0; c8 < 8; c8++)
                eraw[c8] = *(const uint4*)(esrc + (u + 8 * c8) * 8);
        }
        int sy = syms[b * TLEN + t];
        float4 lt = *(const float4*)&gLET[sy * NSTATES + j * 32 + i4];

        // phase 1 (all threads): per-b global max + scale factors (octet reduce)
        float2 mv = *(const float2*)&gM2[p][gb][2 * u];
        float mloc = fmaxf(mv.x, mv.y);
        #pragma unroll
        for (int o = 4; o > 0; o >>= 1)
            mloc = fmaxf(mloc, __shfl_xor_sync(0xffffffffu, mloc, o));
        float scx = __expf(mv.x - mloc), scy = __expf(mv.y - mloc);

        // distribute scales via shuffles: tile(c8) scale lives in octet lane c8,
        // component selected by u>=4
        __half2 sc2[8];
        #pragma unroll
        for (int c8 = 0; c8 < 8; c8++) {
            float vx = __shfl_sync(0xffffffffu, scx, octbase + c8);
            float vy = __shfl_sync(0xffffffffu, scy, octbase + c8);
            float v = (u >= 4) ? vy : vx;
            sc2[c8] = __half2half2(__float2half_rn(v));
        }

        // rotating out-column owner
        if (j == outj) {
            float2 sv = *(const float2*)&gS2[p][gb][2 * u];
            float ps = scx * sv.x + scy * sv.y;
            #pragma unroll
            for (int o = 4; o > 0; o >>= 1)
                ps += __shfl_xor_sync(0xffffffffu, ps, o);
            if (u == 0) out[gb * TLEN + (t - 1)] = mloc + __logf(ps);
        }

        // phase 2: scale pre-loaded E (fp16 hmul2) and store to padded SMEM
        {
            char* edst = sm + E_OFF + b * (ESTR * 2);
            #pragma unroll
            for (int c8 = 0; c8 < 8; c8++) {
                int c = u + 8 * c8;
                uint4 raw = eraw[c8];
                __half2* hp = (__half2*)&raw;
                hp[0] = __hmul2(hp[0], sc2[c8]);
                hp[1] = __hmul2(hp[1], sc2[c8]);
                hp[2] = __hmul2(hp[2], sc2[c8]);
                hp[3] = __hmul2(hp[3], sc2[c8]);
                *(uint4*)(edst + c * 16) = raw;
            }
        }
        __syncthreads();

        // phase 3: HMMA contraction (A in regs, B from SMEM)
        float d0 = 0.f, d1 = 0.f, d2 = 0.f, d3 = 0.f;
        float d4 = 0.f, d5 = 0.f, d6 = 0.f, d7 = 0.f;
        #pragma unroll
        for (int kk = 0; kk < 16; kk++) {
            uint32_t r0, r1, r2, r3;
            ldsm4(r0, r1, r2, r3, b_addr0 + (uint32_t)(kk * 32));
            mma16816(d0, d1, d2, d3, a[kk][0], a[kk][1], a[kk][2], a[kk][3], r0, r1);
            mma16816(d4, d5, d6, d7, a[kk][0], a[kk][1], a[kk][2], a[kk][3], r2, r3);
        }

        // phase 4: stash split-k partials
        {
            int r1r = lane >> 2, c0 = (lane & 3) * 2;
            float* bw = &buf[w * 16 * 18];
            *(float2*)&bw[r1r * 18 + c0]           = make_float2(d0, d1);
            *(float2*)&bw[(r1r + 8) * 18 + c0]     = make_float2(d2, d3);
            *(float2*)&bw[r1r * 18 + c0 + 8]       = make_float2(d4, d5);
            *(float2*)&bw[(r1r + 8) * 18 + c0 + 8] = make_float2(d6, d7);
        }
        __syncthreads();

        // phase 5: epilogue — split-k add, log, +mb+em, publish
        {
            const int nib = b >> 4, cb = b & 15;
            const int mis = i4 >> 4, rbase = i4 & 15;
            const float* b0p = &buf[(mis + 2 * nib) * 288 + cb];
            const float* b1p = b0p + 4 * 288;
            float C0 = b0p[(rbase + 0) * 18] + b1p[(rbase + 0) * 18];
            float C1 = b0p[(rbase + 1) * 18] + b1p[(rbase + 1) * 18];
            float C2 = b0p[(rbase + 2) * 18] + b1p[(rbase + 2) * 18];
            float C3 = b0p[(rbase + 3) * 18] + b1p[(rbase + 3) * 18];
            float v0 = __logf(C0) + mloc + lt.x;
            float v1 = __logf(C1) + mloc + lt.y;
            float v2 = __logf(C2) + mloc + lt.z;
            float v3 = __logf(C3) + mloc + lt.w;
            float m = fmaxf(fmaxf(v0, v1), fmaxf(v2, v3));
            #pragma unroll
            for (int o = 4; o > 0; o >>= 1) m = fmaxf(m, __shfl_xor_sync(0xffffffffu, m, o));
            float e0 = __expf(v0 - m), e1 = __expf(v1 - m), e2 = __expf(v2 - m), e3 = __expf(v3 - m);
            float s = e0 + e1 + e2 + e3;
            #pragma unroll
            for (int o = 4; o > 0; o >>= 1) s += __shfl_xor_sync(0xffffffffu, s, o);
            union { __half2 h[2]; uint2 uu; } cv;
            cv.h[0] = __floats2half2_rn(e0, e1);
            cv.h[1] = __floats2half2_rn(e2, e3);
            *(uint2*)&gEh[q][gb][j * 32 + i4] = cv.uu;
            if (u == 0) { gM2[q][gb][j] = m; gS2[q][gb][j] = s; }
        }

        groupbar(my_cnt, target); target += GI;
    }

    // final output column t = 255 (buffer 1), owned by j == 15
    if (j == 15 && tid < 32) {
        const int p = (TLEN - 1) & 1;
        int gbb = g * 32 + tid;
        const float* mrow = &gM2[p][gbb][0];
        const float* srow = &gS2[p][gbb][0];
        float mb = mrow[0];
        #pragma unroll
        for (int jj = 1; jj < 16; jj++) mb = fmaxf(mb, mrow[jj]);
        float ssum = 0.f;
        #pragma unroll
        for (int jj = 0; jj < 16; jj++) ssum += __expf(mrow[jj] - mb) * srow[jj];
        out[gbb * TLEN + (TLEN - 1)] = mb + __logf(ssum);
    }
}

// ---------------- launch ----------------
extern "C" void kernel_launch(void* const* d_in, const int* in_sizes, int n_in,
                              void* d_out, int out_size) {
    const int*   batch = (const int*)d_in[0];
    const float* em    = (const float*)d_in[1];
    const float* tr    = (const float*)d_in[2];
    const float* pr    = (const float*)d_in[3];
    float* out = (float*)d_out;

    cudaFuncSetAttribute(forward_kernel, cudaFuncAttributeMaxDynamicSharedMemorySize, SMEM_TOTAL);

    k_prep<<<NSTATES + 1, 256>>>(em, tr, pr);
    forward_kernel<<<NCTA, NT, SMEM_TOTAL>>>(batch, out);
}

// round 8
// speedup vs baseline: 1.3901x; 1.1504x over previous
#include <cuda_runtime.h>
#include <cuda_fp16.h>
#include <cstdint>

#define NSTATES 512
#define MSYMS   256
#define BATCHN  256
#define TLEN    256

#define GB 16                // batch groups (clusters)
#define GI 8                 // i-slices per group = cluster size
#define NB 16                // batch elements per group
#define MI 64                // states per CTA
#define NCTA (GB*GI)         // 128 CTAs
#define NT 256               // 8 warps

#define ESTR 520             // fp16 row stride (1040B), 16B aligned

// ---- dynamic SMEM layout (bytes) ----
#define BUF_OFF    0                     // float[8][16][18] = 9216
#define STATS_OFF  9216                  // float2 [2][16 b][8 j] = 2048
#define MB_OFF     11264                 // float[16] = 64
#define P_OFF      11328                 // 64 x 520 fp16 = 66560
#define E_OFF      77888                 // 16 x 520 fp16 = 16640
#define SYMS_OFF   94528                 // 16 x 256 int  = 16384
#define SMEM_TOTAL 110912

// ---------------- device globals ----------------
__device__ __half gPh[NSTATES * NSTATES];   // column-softmax of transition, fp16
__device__ float  gLET[MSYMS * NSTATES];    // log emission transposed [sym][state]
__device__ float  gLP[NSTATES];             // log priors
__device__ __half gEh[2][BATCHN][NSTATES];  // exp(alpha - tile_max), fp16, dbl-buffered

// ---------------- PTX helpers (sm_90 baseline ISA only) ----------------
__device__ __forceinline__ uint32_t smem_u32(const void* p) {
    uint32_t a;
    asm("{ .reg .u64 t; cvta.to.shared.u64 t, %1; cvt.u32.u64 %0, t; }" : "=r"(a) : "l"(p));
    return a;
}
__device__ __forceinline__ uint32_t cluster_rank() {
    uint32_t r; asm("mov.u32 %0, %%cluster_ctarank;" : "=r"(r)); return r;
}
#define CLUSTER_ARRIVE() asm volatile("barrier.cluster.arrive.aligned;" ::: "memory")
#define CLUSTER_WAIT()   asm volatile("barrier.cluster.wait.aligned;"   ::: "memory")

__device__ __forceinline__ void dsmem_st_pair(uint32_t laddr, uint32_t rank, float mx, float sx) {
    asm volatile(
        "{\n\t.reg .b32 r;\n\t"
        "mapa.shared::cluster.u32 r, %0, %1;\n\t"
        "st.shared::cluster.f32 [r], %2;\n\t"
        "st.shared::cluster.f32 [r+4], %3;\n\t}"
        :: "r"(laddr), "r"(rank), "f"(mx), "f"(sx) : "memory");
}
__device__ __forceinline__ void ldsm4(uint32_t& r0, uint32_t& r1, uint32_t& r2, uint32_t& r3,
                                      uint32_t addr) {
    asm volatile("ldmatrix.sync.aligned.m8n8.x4.shared.b16 {%0,%1,%2,%3}, [%4];"
                 : "=r"(r0), "=r"(r1), "=r"(r2), "=r"(r3) : "r"(addr));
}
__device__ __forceinline__ void mma16816(float& d0, float& d1, float& d2, float& d3,
                                         uint32_t a0, uint32_t a1, uint32_t a2, uint32_t a3,
                                         uint32_t b0, uint32_t b1) {
    asm volatile(
        "mma.sync.aligned.m16n8k16.row.col.f32.f16.f16.f32 "
        "{%0,%1,%2,%3}, {%4,%5,%6,%7}, {%8,%9}, {%0,%1,%2,%3};"
        : "+f"(d0), "+f"(d1), "+f"(d2), "+f"(d3)
        : "r"(a0), "r"(a1), "r"(a2), "r"(a3), "r"(b0), "r"(b1));
}

// ---------------- fused prep kernel ----------------
__global__ void k_prep(const float* __restrict__ em, const float* __restrict__ tr,
                       const float* __restrict__ pr) {
    __shared__ float red[256];
    const int blk = blockIdx.x, t = threadIdx.x;

    if (blk < NSTATES) {
        float x = em[blk * MSYMS + t];
        red[t] = x; __syncthreads();
        for (int s = 128; s > 0; s >>= 1) { if (t < s) red[t] = fmaxf(red[t], red[t + s]); __syncthreads(); }
        float m = red[0]; __syncthreads();
        red[t] = __expf(x - m); __syncthreads();
        for (int s = 128; s > 0; s >>= 1) { if (t < s) red[t] += red[t + s]; __syncthreads(); }
        float lse = m + __logf(red[0]);
        gLET[t * NSTATES + blk] = x - lse;
        __syncthreads();

        float x0 = tr[t * NSTATES + blk];
        float x1 = tr[(t + 256) * NSTATES + blk];
        red[t] = fmaxf(x0, x1); __syncthreads();
        for (int s = 128; s > 0; s >>= 1) { if (t < s) red[t] = fmaxf(red[t], red[t + s]); __syncthreads(); }
        float mm = red[0]; __syncthreads();
        red[t] = __expf(x0 - mm) + __expf(x1 - mm); __syncthreads();
        for (int s = 128; s > 0; s >>= 1) { if (t < s) red[t] += red[t + s]; __syncthreads(); }
        float clse = mm + __logf(red[0]);
        gPh[t * NSTATES + blk]         = __float2half_rn(__expf(x0 - clse));
        gPh[(t + 256) * NSTATES + blk] = __float2half_rn(__expf(x1 - clse));
    } else {
        float x0 = pr[t], x1 = pr[t + 256];
        red[t] = fmaxf(x0, x1); __syncthreads();
        for (int s = 128; s > 0; s >>= 1) { if (t < s) red[t] = fmaxf(red[t], red[t + s]); __syncthreads(); }
        float m = red[0]; __syncthreads();
        red[t] = __expf(x0 - m) + __expf(x1 - m); __syncthreads();
        for (int s = 128; s > 0; s >>= 1) { if (t < s) red[t] += red[t + s]; __syncthreads(); }
        float lse = m + __logf(red[0]);
        gLP[t]       = x0 - lse;
        gLP[t + 256] = x1 - lse;
    }
}

// ---------------- forward kernel (8-CTA clusters) ----------------
extern __shared__ char sm_raw[];

__global__ void __launch_bounds__(NT, 1) forward_kernel(const int* __restrict__ batch,
                                                        float* __restrict__ out) {
    char* sm = sm_raw;
    const uint32_t smem_base = smem_u32(sm);
    float* buf    = (float*)(sm + BUF_OFF);     // [8][16][18]
    float* sm_mbf = (float*)(sm + MB_OFF);      // [16]
    int*   syms   = (int*)(sm + SYMS_OFF);      // [16][256]
    const uint32_t P_base = smem_base + P_OFF;
    const uint32_t E_base = smem_base + E_OFF;
    const uint32_t ST_base = smem_base + STATS_OFF;

    const int tid  = threadIdx.x;
    const int lane = tid & 31;
    const int w    = tid >> 5;
    const int g    = blockIdx.x >> 3;        // 0..15 batch group
    const int j    = (int)cluster_rank();    // 0..7 i-slice

    // staging/stats mapping
    const int bb   = (tid >> 3) & 15;        // 0..15 batch row
    const int u    = tid & 7;                // tile index within octet
    const int team = tid >> 7;               // 0/1
    const int octbase = lane & 24;

    // epilogue mapping: thread owns (b2, iq..iq+3)
    const int b2 = tid >> 4;                 // 0..15
    const int iq = (tid & 15) * 4;           // 0..60
    const int gb2 = g * NB + b2;

    // warp tile: mi in 0..3 (m16), kh in 0..1 (k256)
    const int mi = w & 3, kh = (w >> 2) & 1;
    const int kbase = kh * 256;

    // ---------------- prologue ----------------
    // P j-slice (64 x 512 fp16) -> padded SMEM rows
    #pragma unroll
    for (int it = 0; it < 16; it++) {
        int idx = tid + NT * it;             // 0..4095
        int row = idx >> 6, c = idx & 63;
        *(uint4*)(sm + P_OFF + row * (ESTR * 2) + c * 16) =
            *(const uint4*)(&gPh[(j * MI + row) * NSTATES] + c * 8);
    }
    // symbols for my 16 batch rows
    for (int idx = tid; idx < NB * TLEN; idx += NT)
        syms[idx] = batch[(g * NB + (idx >> 8)) * TLEN + (idx & 255)];
    __syncthreads();

    // A fragments resident in registers
    uint32_t a[16][4];
    {
        const int arow  = mi * 16 + (lane & 15);
        const int akoff = (lane >> 4) * 8;
        #pragma unroll
        for (int kk = 0; kk < 16; kk++) {
            uint32_t addr = P_base + (uint32_t)((arow * ESTR + kbase + kk * 16 + akoff) * 2);
            ldsm4(a[kk][0], a[kk][1], a[kk][2], a[kk][3], addr);
        }
    }
    // B ldmatrix base (16 rows)
    const int brow = (lane >> 4) * 8 + (lane & 7);
    const int bk0  = ((lane >> 3) & 1) * 8 + kbase;
    const uint32_t b_addr0 = E_base + (uint32_t)((brow * ESTR + bk0) * 2);

    // ---------------- step 0 ----------------
    {
        int sy = syms[b2 * TLEN + 0];
        float4 lt = *(const float4*)&gLET[sy * NSTATES + j * MI + iq];
        float4 lp = *(const float4*)&gLP[j * MI + iq];
        float v0 = lt.x + lp.x, v1 = lt.y + lp.y, v2 = lt.z + lp.z, v3 = lt.w + lp.w;
        float m = fmaxf(fmaxf(v0, v1), fmaxf(v2, v3));
        #pragma unroll
        for (int o = 8; o > 0; o >>= 1) m = fmaxf(m, __shfl_xor_sync(0xffffffffu, m, o));
        float e0 = __expf(v0 - m), e1 = __expf(v1 - m), e2 = __expf(v2 - m), e3 = __expf(v3 - m);
        float s = e0 + e1 + e2 + e3;
        #pragma unroll
        for (int o = 8; o > 0; o >>= 1) s += __shfl_xor_sync(0xffffffffu, s, o);
        union { __half2 h[2]; uint2 uu; } cv;
        cv.h[0] = __floats2half2_rn(e0, e1);
        cv.h[1] = __floats2half2_rn(e2, e3);
        *(uint2*)&gEh[0][gb2][j * MI + iq] = cv.uu;
        if ((tid & 15) == 0) {
            uint32_t laddr = ST_base + 0 * 1024 + b2 * 64 + j * 8;
            #pragma unroll
            for (int r = 0; r < GI; r++) dsmem_st_pair(laddr, r, m, s);
        }
        CLUSTER_ARRIVE();
    }

    // ---------------- main loop ----------------
    for (int t = 1; t < TLEN; ++t) {
        const int p = (t - 1) & 1, q = t & 1;
        const int outj = (t - 1) & 7;

        // prefetch (peer-independent) before the wait
        int sy = syms[b2 * TLEN + t];
        float4 lt = *(const float4*)&gLET[sy * NSTATES + j * MI + iq];

        CLUSTER_WAIT();

        // phase 0: raw E loads (L2) — longest pole, issue first
        uint4 eraw[4];
        {
            const __half* esrc = &gEh[p][g * NB + bb][0];
            #pragma unroll
            for (int c8 = 0; c8 < 4; c8++) {
                int c = u + 32 * team + 8 * c8;
                eraw[c8] = *(const uint4*)(esrc + c * 8);
            }
        }

        // phase 1: stats from LOCAL SMEM (DSMEM-delivered), octet reduce
        float2 pr2 = *(float2*)(sm + STATS_OFF + p * 1024 + bb * 64 + u * 8);
        float mloc = pr2.x;
        #pragma unroll
        for (int o = 4; o > 0; o >>= 1)
            mloc = fmaxf(mloc, __shfl_xor_sync(0xffffffffu, mloc, o));
        float scx = __expf(pr2.x - mloc);
        if (team == 0 && u == 0) sm_mbf[bb] = mloc;

        // rotating out-column owner
        if (j == outj && team == 0) {
            float ps = scx * pr2.y;
            #pragma unroll
            for (int o = 4; o > 0; o >>= 1)
                ps += __shfl_xor_sync(0xffffffffu, ps, o);
            if (u == 0) out[(g * NB + bb) * TLEN + (t - 1)] = mloc + __logf(ps);
        }

        // phase 2: scale E (chunk c entirely in tile 4*team+c8) and stage to SMEM
        {
            char* edst = sm + E_OFF + bb * (ESTR * 2);
            #pragma unroll
            for (int c8 = 0; c8 < 4; c8++) {
                float v = __shfl_sync(0xffffffffu, scx, octbase + 4 * team + c8);
                __half2 sc2 = __half2half2(__float2half_rn(v));
                int c = u + 32 * team + 8 * c8;
                uint4 raw = eraw[c8];
                __half2* hp = (__half2*)&raw;
                hp[0] = __hmul2(hp[0], sc2);
                hp[1] = __hmul2(hp[1], sc2);
                hp[2] = __hmul2(hp[2], sc2);
                hp[3] = __hmul2(hp[3], sc2);
                *(uint4*)(edst + c * 16) = raw;
            }
        }
        __syncthreads();

        // phase 3: HMMA (A in regs, B from SMEM)
        float d0 = 0.f, d1 = 0.f, d2 = 0.f, d3 = 0.f;
        float d4 = 0.f, d5 = 0.f, d6 = 0.f, d7 = 0.f;
        #pragma unroll
        for (int kk = 0; kk < 16; kk++) {
            uint32_t r0, r1, r2, r3;
            ldsm4(r0, r1, r2, r3, b_addr0 + (uint32_t)(kk * 32));
            mma16816(d0, d1, d2, d3, a[kk][0], a[kk][1], a[kk][2], a[kk][3], r0, r1);
            mma16816(d4, d5, d6, d7, a[kk][0], a[kk][1], a[kk][2], a[kk][3], r2, r3);
        }

        // phase 4: stash split-k partials
        {
            int r1r = lane >> 2, c0 = (lane & 3) * 2;
            float* bw = &buf[w * 16 * 18];
            *(float2*)&bw[r1r * 18 + c0]           = make_float2(d0, d1);
            *(float2*)&bw[(r1r + 8) * 18 + c0]     = make_float2(d2, d3);
            *(float2*)&bw[r1r * 18 + c0 + 8]       = make_float2(d4, d5);
            *(float2*)&bw[(r1r + 8) * 18 + c0 + 8] = make_float2(d6, d7);
        }
        __syncthreads();

        // phase 5: epilogue — split-k add, log, +mb+em, publish E + stats
        {
            const int mis = iq >> 4, rbase = iq & 15;
            const float* b0p = &buf[mis * 288 + b2];
            const float* b1p = b0p + 4 * 288;
            float C0 = b0p[(rbase + 0) * 18] + b1p[(rbase + 0) * 18];
            float C1 = b0p[(rbase + 1) * 18] + b1p[(rbase + 1) * 18];
            float C2 = b0p[(rbase + 2) * 18] + b1p[(rbase + 2) * 18];
            float C3 = b0p[(rbase + 3) * 18] + b1p[(rbase + 3) * 18];
            float mbv = sm_mbf[b2];
            float v0 = __logf(C0) + mbv + lt.x;
            float v1 = __logf(C1) + mbv + lt.y;
            float v2 = __logf(C2) + mbv + lt.z;
            float v3 = __logf(C3) + mbv + lt.w;
            float m = fmaxf(fmaxf(v0, v1), fmaxf(v2, v3));
            #pragma unroll
            for (int o = 8; o > 0; o >>= 1) m = fmaxf(m, __shfl_xor_sync(0xffffffffu, m, o));
            float e0 = __expf(v0 - m), e1 = __expf(v1 - m), e2 = __expf(v2 - m), e3 = __expf(v3 - m);
            float s = e0 + e1 + e2 + e3;
            #pragma unroll
            for (int o = 8; o > 0; o >>= 1) s += __shfl_xor_sync(0xffffffffu, s, o);
            union { __half2 h[2]; uint2 uu; } cv;
            cv.h[0] = __floats2half2_rn(e0, e1);
            cv.h[1] = __floats2half2_rn(e2, e3);
            *(uint2*)&gEh[q][gb2][j * MI + iq] = cv.uu;
            if ((tid & 15) == 0) {
                uint32_t laddr = ST_base + q * 1024 + b2 * 64 + j * 8;
                #pragma unroll
                for (int r = 0; r < GI; r++) dsmem_st_pair(laddr, r, m, s);
            }
        }

        CLUSTER_ARRIVE();
    }

    // final column t=255 (stats buffer 1), owner j == 7
    CLUSTER_WAIT();
    if (j == 7 && tid < NB) {
        const float2* st = (const float2*)(sm + STATS_OFF + 1024 + tid * 64);
        float mb = st[0].x;
        #pragma unroll
        for (int jj = 1; jj < GI; jj++) mb = fmaxf(mb, st[jj].x);
        float ssum = 0.f;
        #pragma unroll
        for (int jj = 0; jj < GI; jj++) ssum += __expf(st[jj].x - mb) * st[jj].y;
        out[(g * NB + tid) * TLEN + (TLEN - 1)] = mb + __logf(ssum);
    }
}

// ---------------- launch ----------------
extern "C" void kernel_launch(void* const* d_in, const int* in_sizes, int n_in,
                              void* d_out, int out_size) {
    const int*   batch = (const int*)d_in[0];
    const float* em    = (const float*)d_in[1];
    const float* tr    = (const float*)d_in[2];
    const float* pr    = (const float*)d_in[3];
    float* out = (float*)d_out;

    cudaFuncSetAttribute(forward_kernel, cudaFuncAttributeMaxDynamicSharedMemorySize, SMEM_TOTAL);

    k_prep<<<NSTATES + 1, 256>>>(em, tr, pr);

    cudaLaunchConfig_t cfg = {};
    cfg.gridDim = dim3(NCTA, 1, 1);
    cfg.blockDim = dim3(NT, 1, 1);
    cfg.dynamicSmemBytes = SMEM_TOTAL;
    cfg.stream = 0;
    cudaLaunchAttribute attrs[1];
    attrs[0].id = cudaLaunchAttributeClusterDimension;
    attrs[0].val.clusterDim.x = GI;
    attrs[0].val.clusterDim.y = 1;
    attrs[0].val.clusterDim.z = 1;
    cfg.attrs = attrs;
    cfg.numAttrs = 1;
    cudaLaunchKernelEx(&cfg, forward_kernel, batch, out);
}